// round 15
// baseline (speedup 1.0000x reference)
#include <cuda_runtime.h>
#include <cstdint>

#define N_NODES 50000
#define HIDDEN  64
#define INDIM   512
#define OUTDIM  40

// Scratch (device globals)
__device__ __align__(16) float g_hs[N_NODES * HIDDEN];    // dinv[i] * h[i]
__device__ __align__(16) float g_agg[N_NODES * HIDDEN];   // raw sums (pre-dinv[dst])
__device__ __align__(16) float g_deg[N_NODES];
__device__ __align__(16) float g_dinv[N_NODES];

// ---------------------------------------------------------------------------
// Degree: deg[i] = 1 (self loop) + #edges with dst==i
// ---------------------------------------------------------------------------
__global__ void init_deg_kernel(int n) {
    int i = blockIdx.x * blockDim.x + threadIdx.x;
    if (i < n) g_deg[i] = 1.0f;
}

__global__ void deg_accum_kernel(const int* __restrict__ dst, int E, int n) {
    int e = blockIdx.x * blockDim.x + threadIdx.x;
    if (e < E) {
        int d = dst[e];
        if ((unsigned)d < (unsigned)n) atomicAdd(&g_deg[d], 1.0f);
    }
}

// dinv = rsqrt(deg)
__global__ void dinv_kernel(int n) {
    int i = blockIdx.x * blockDim.x + threadIdx.x;
    if (i < n) g_dinv[i] = rsqrtf(g_deg[i]);
}

// ---------------------------------------------------------------------------
// GEMM1 (tensor cores, tf32): h[n,64] = X[n,512] @ W1[512,64]
// 64 rows/block, 256 threads, 8 warps: warp = (m16 tile, 32-col half).
// High occupancy (4 blocks/SM) to hide X DRAM latency.
// Fused epilogue: hs = dinv*h; agg_raw = hs.
// ---------------------------------------------------------------------------
__device__ __forceinline__ uint32_t f2tf32(float f) {
    uint32_t r;
    asm("cvt.rna.tf32.f32 %0, %1;" : "=r"(r) : "f"(f));
    return r;
}

#define XS_STRIDE 36
#define WS_STRIDE 72

__global__ __launch_bounds__(256) void gemm1_mma_kernel(
    const float* __restrict__ X, const float* __restrict__ W, int n)
{
    __shared__ uint32_t Xs[64 * XS_STRIDE];
    __shared__ uint32_t Ws[32 * WS_STRIDE];

    const int tid  = threadIdx.x;
    const int lane = tid & 31;
    const int wid  = tid >> 5;        // 0..7
    const int gid  = lane >> 2;       // 0..7
    const int tig  = lane & 3;        // 0..3
    const int mt   = wid & 3;         // m-tile 0..3 (16 rows each)
    const int nh   = wid >> 2;        // col half 0/1 (32 cols each)
    const int row0 = blockIdx.x * 64;

    float acc[4][4] = {};

    for (int k0 = 0; k0 < INDIM; k0 += 32) {
        // X tile: 64 rows x 32 k = 512 float4 slots / 256 threads = 2 each
        #pragma unroll
        for (int t = 0; t < 2; t++) {
            int s = t * 256 + tid;
            int r = s >> 3, q = s & 7;
            int rr = row0 + r; if (rr >= n) rr = n - 1;
            float4 v = *(const float4*)(X + (size_t)rr * INDIM + k0 + q * 4);
            uint4 u = make_uint4(f2tf32(v.x), f2tf32(v.y), f2tf32(v.z), f2tf32(v.w));
            *(uint4*)(Xs + r * XS_STRIDE + q * 4) = u;
        }
        // W tile: 32 k x 64 cols = 512 float4 / 256 threads = 2 each
        #pragma unroll
        for (int t = 0; t < 2; t++) {
            int s = t * 256 + tid;
            int kk = s >> 4, q = s & 15;
            float4 v = *(const float4*)(W + (size_t)(k0 + kk) * HIDDEN + q * 4);
            uint4 u = make_uint4(f2tf32(v.x), f2tf32(v.y), f2tf32(v.z), f2tf32(v.w));
            *(uint4*)(Ws + kk * WS_STRIDE + q * 4) = u;
        }
        __syncthreads();

        #pragma unroll
        for (int kk = 0; kk < 32; kk += 8) {
            int rbase = mt * 16;
            uint32_t a0 = Xs[(rbase + gid) * XS_STRIDE + kk + tig];
            uint32_t a1 = Xs[(rbase + gid + 8) * XS_STRIDE + kk + tig];
            uint32_t a2 = Xs[(rbase + gid) * XS_STRIDE + kk + tig + 4];
            uint32_t a3 = Xs[(rbase + gid + 8) * XS_STRIDE + kk + tig + 4];
            #pragma unroll
            for (int nbl = 0; nbl < 4; nbl++) {
                int nb = nh * 4 + nbl;
                uint32_t b0 = Ws[(kk + tig) * WS_STRIDE + nb * 8 + gid];
                uint32_t b1 = Ws[(kk + tig + 4) * WS_STRIDE + nb * 8 + gid];
                asm volatile(
                    "mma.sync.aligned.m16n8k8.row.col.f32.tf32.tf32.f32 "
                    "{%0,%1,%2,%3}, {%4,%5,%6,%7}, {%8,%9}, {%0,%1,%2,%3};"
                    : "+f"(acc[nbl][0]), "+f"(acc[nbl][1]),
                      "+f"(acc[nbl][2]), "+f"(acc[nbl][3])
                    : "r"(a0), "r"(a1), "r"(a2), "r"(a3), "r"(b0), "r"(b1));
            }
        }
        __syncthreads();
    }

    // Fused epilogue: hs = dinv*h; agg_raw = hs (dinv[dst] deferred to gemm2)
    const int rA = row0 + mt * 16 + gid;
    const int rB = rA + 8;
    float dA = (rA < n) ? g_dinv[rA] : 0.f;
    float dB = (rB < n) ? g_dinv[rB] : 0.f;
    #pragma unroll
    for (int nbl = 0; nbl < 4; nbl++) {
        int col = (nh * 4 + nbl) * 8 + 2 * tig;
        if (rA < n) {
            float2 h01 = make_float2(dA * acc[nbl][0], dA * acc[nbl][1]);
            *(float2*)(g_hs  + (size_t)rA * HIDDEN + col) = h01;
            *(float2*)(g_agg + (size_t)rA * HIDDEN + col) = h01;
        }
        if (rB < n) {
            float2 h23 = make_float2(dB * acc[nbl][2], dB * acc[nbl][3]);
            *(float2*)(g_hs  + (size_t)rB * HIDDEN + col) = h23;
            *(float2*)(g_agg + (size_t)rB * HIDDEN + col) = h23;
        }
    }
}

// ---------------------------------------------------------------------------
// Edge scatter: agg_raw[dst,:] += hs[src,:]  (pure gather + reduction)
// 8-thread groups, 2 edges per thread: 4 independent full-line gathers
// + 4 independent v4 reductions per thread.
// ---------------------------------------------------------------------------
__device__ __forceinline__ void red_add_v4(float* addr, float4 v) {
    asm volatile("red.global.add.v4.f32 [%0], {%1, %2, %3, %4};"
                 :: "l"(__cvta_generic_to_global(addr)),
                    "f"(v.x), "f"(v.y), "f"(v.z), "f"(v.w)
                 : "memory");
}

__global__ __launch_bounds__(256) void scatter_kernel(
    const int* __restrict__ src, const int* __restrict__ dst, int E, int n)
{
    int idx = blockIdx.x * blockDim.x + threadIdx.x;
    int g = idx >> 3, q = idx & 7;        // group of 8 threads owns edges 2g, 2g+1
    int e0 = 2 * g, e1 = 2 * g + 1;
    if (e0 >= E) return;
    bool has1 = (e1 < E);

    int2 ss = *(const int2*)(src + e0);   // e0 even -> 8B aligned
    int2 dd = *(const int2*)(dst + e0);

    bool ok0 = (unsigned)ss.x < (unsigned)n && (unsigned)dd.x < (unsigned)n;
    bool ok1 = has1 && (unsigned)ss.y < (unsigned)n && (unsigned)dd.y < (unsigned)n;

    if (ok0 && ok1) {
        const float4* h0 = (const float4*)g_hs + ss.x * 16;
        const float4* h1 = (const float4*)g_hs + ss.y * 16;
        float4 v00 = __ldg(h0 + q);
        float4 v01 = __ldg(h0 + q + 8);
        float4 v10 = __ldg(h1 + q);
        float4 v11 = __ldg(h1 + q + 8);
        float* b0 = g_agg + (size_t)dd.x * HIDDEN;
        float* b1 = g_agg + (size_t)dd.y * HIDDEN;
        red_add_v4(b0 + q * 4, v00);
        red_add_v4(b0 + (q + 8) * 4, v01);
        red_add_v4(b1 + q * 4, v10);
        red_add_v4(b1 + (q + 8) * 4, v11);
    } else if (ok0) {
        const float4* h0 = (const float4*)g_hs + ss.x * 16;
        float4 v00 = __ldg(h0 + q);
        float4 v01 = __ldg(h0 + q + 8);
        float* b0 = g_agg + (size_t)dd.x * HIDDEN;
        red_add_v4(b0 + q * 4, v00);
        red_add_v4(b0 + (q + 8) * 4, v01);
    } else if (ok1) {
        const float4* h1 = (const float4*)g_hs + ss.y * 16;
        float4 v10 = __ldg(h1 + q);
        float4 v11 = __ldg(h1 + q + 8);
        float* b1 = g_agg + (size_t)dd.y * HIDDEN;
        red_add_v4(b1 + q * 4, v10);
        red_add_v4(b1 + (q + 8) * 4, v11);
    }
}

// ---------------------------------------------------------------------------
// GEMM2: out[n,40] = relu(dinv[row]*agg_raw + b1) @ Wfc^T + bfc
// ---------------------------------------------------------------------------
__global__ __launch_bounds__(240) void gemm2_kernel(
    const float* __restrict__ b1, const float* __restrict__ Wfc,
    const float* __restrict__ bfc, float* __restrict__ out, int n)
{
    __shared__ float hs[24 * 68];
    __shared__ float Wt[64 * 40];
    __shared__ float bfs[40];

    const int tx = threadIdx.x;     // 0..9
    const int ty = threadIdx.y;     // 0..23
    const int tid = ty * 10 + tx;

    for (int idx = tid; idx < 64 * 40; idx += 240) {
        int o = idx % 40, j = idx / 40;
        Wt[j * 40 + o] = Wfc[o * 64 + j];
    }
    if (tid < 40) bfs[tid] = bfc[tid];

    const int row0 = blockIdx.x * 24;
    for (int idx = tid; idx < 24 * 16; idx += 240) {
        int r = idx >> 4, q = idx & 15;
        int grow = row0 + r;
        float4 v = make_float4(0.f, 0.f, 0.f, 0.f);
        if (grow < n) {
            float dv = g_dinv[grow];
            v = ((const float4*)g_agg)[grow * 16 + q];
            float4 bb = ((const float4*)b1)[q];
            v.x = fmaxf(fmaf(dv, v.x, bb.x), 0.f);
            v.y = fmaxf(fmaf(dv, v.y, bb.y), 0.f);
            v.z = fmaxf(fmaf(dv, v.z, bb.z), 0.f);
            v.w = fmaxf(fmaf(dv, v.w, bb.w), 0.f);
        }
        *(float4*)(hs + r * 68 + q * 4) = v;
    }
    __syncthreads();

    float4 acc = make_float4(0.f, 0.f, 0.f, 0.f);
    #pragma unroll
    for (int j = 0; j < 64; j++) {
        float h = hs[ty * 68 + j];
        float4 w = *(const float4*)(Wt + j * 40 + tx * 4);
        acc.x += h * w.x;
        acc.y += h * w.y;
        acc.z += h * w.z;
        acc.w += h * w.w;
    }

    int grow = row0 + ty;
    if (grow < n) {
        float4 bb = *(const float4*)(bfs + tx * 4);
        acc.x += bb.x; acc.y += bb.y; acc.z += bb.z; acc.w += bb.w;
        *(float4*)(out + (size_t)grow * OUTDIM + tx * 4) = acc;
    }
}

// ---------------------------------------------------------------------------
extern "C" void kernel_launch(void* const* d_in, const int* in_sizes, int n_in,
                              void* d_out, int out_size)
{
    const float* X     = (const float*)d_in[0];
    const int*   edges = (const int*)d_in[1];     // int64 downcast to int32 by harness
    const float* W1    = (const float*)d_in[2];
    const float* b1    = (const float*)d_in[3];
    const float* Wfc   = (const float*)d_in[4];
    const float* bfc   = (const float*)d_in[5];
    float* out = (float*)d_out;

    const int n = in_sizes[0] / INDIM;
    const int E = in_sizes[1] / 2;
    const int* src = edges;
    const int* dst = edges + E;

    init_deg_kernel<<<(n + 255) / 256, 256>>>(n);
    deg_accum_kernel<<<(E + 255) / 256, 256>>>(dst, E, n);
    dinv_kernel<<<(n + 255) / 256, 256>>>(n);
    gemm1_mma_kernel<<<(n + 63) / 64, 256>>>(X, W1, n);
    int groups = (E + 1) / 2;
    scatter_kernel<<<(groups * 8 + 255) / 256, 256>>>(src, dst, E, n);
    gemm2_kernel<<<(n + 23) / 24, dim3(10, 24)>>>(b1, Wfc, bfc, out, n);
}

// round 16
// speedup vs baseline: 1.0024x; 1.0024x over previous
#include <cuda_runtime.h>
#include <cstdint>

#define N_NODES 50000
#define HIDDEN  64
#define INDIM   512
#define OUTDIM  40

// Scratch (device globals)
__device__ __align__(16) float g_hs[N_NODES * HIDDEN];    // dinv[i] * h[i]
__device__ __align__(16) float g_agg[N_NODES * HIDDEN];   // raw sums (pre-dinv[dst])
__device__ __align__(16) float g_deg[N_NODES];
__device__ __align__(16) float g_dinv[N_NODES];

// ---------------------------------------------------------------------------
// Degree: deg[i] = 1 (self loop) + #edges with dst==i
// ---------------------------------------------------------------------------
__global__ void init_deg_kernel(int n) {
    int i = blockIdx.x * blockDim.x + threadIdx.x;
    if (i < n) g_deg[i] = 1.0f;
}

__global__ void deg_accum_kernel(const int* __restrict__ dst, int E, int n) {
    int e = blockIdx.x * blockDim.x + threadIdx.x;
    if (e < E) {
        int d = dst[e];
        if ((unsigned)d < (unsigned)n) atomicAdd(&g_deg[d], 1.0f);
    }
}

// dinv = rsqrt(deg)
__global__ void dinv_kernel(int n) {
    int i = blockIdx.x * blockDim.x + threadIdx.x;
    if (i < n) g_dinv[i] = rsqrtf(g_deg[i]);
}

// ---------------------------------------------------------------------------
// GEMM1 (tensor cores, tf32): h[n,64] = X[n,512] @ W1[512,64]
// 256 rows/block, 8 warps x 32 rows (2 m-tiles sharing B fragments).
// Minimizes W reload traffic (196 blocks x 131KB = 26MB) and LDS/MMA ratio.
// Fused epilogue: hs = dinv*h; agg_raw = hs.
// ---------------------------------------------------------------------------
__device__ __forceinline__ uint32_t f2tf32(float f) {
    uint32_t r;
    asm("cvt.rna.tf32.f32 %0, %1;" : "=r"(r) : "f"(f));
    return r;
}

#define XS_STRIDE 36
#define WS_STRIDE 72

__global__ __launch_bounds__(256, 2) void gemm1_mma_kernel(
    const float* __restrict__ X, const float* __restrict__ W, int n)
{
    __shared__ uint32_t Xs[256 * XS_STRIDE];
    __shared__ uint32_t Ws[32 * WS_STRIDE];

    const int tid  = threadIdx.x;
    const int lane = tid & 31;
    const int wid  = tid >> 5;        // 0..7
    const int gid  = lane >> 2;       // 0..7
    const int tig  = lane & 3;        // 0..3
    const int wrow = wid * 32;        // warp covers 32 rows
    const int row0 = blockIdx.x * 256;

    float acc[2][8][4] = {};

    for (int k0 = 0; k0 < INDIM; k0 += 32) {
        // X tile: 256 rows x 32 k = 2048 float4 slots / 256 threads = 8 each
        #pragma unroll
        for (int t = 0; t < 8; t++) {
            int s = t * 256 + tid;
            int r = s >> 3, q = s & 7;
            int rr = row0 + r; if (rr >= n) rr = n - 1;
            float4 v = *(const float4*)(X + (size_t)rr * INDIM + k0 + q * 4);
            uint4 u = make_uint4(f2tf32(v.x), f2tf32(v.y), f2tf32(v.z), f2tf32(v.w));
            *(uint4*)(Xs + r * XS_STRIDE + q * 4) = u;
        }
        // W tile: 32 k x 64 cols = 512 float4 / 256 threads = 2 each
        #pragma unroll
        for (int t = 0; t < 2; t++) {
            int s = t * 256 + tid;
            int kk = s >> 4, q = s & 15;
            float4 v = *(const float4*)(W + (size_t)(k0 + kk) * HIDDEN + q * 4);
            uint4 u = make_uint4(f2tf32(v.x), f2tf32(v.y), f2tf32(v.z), f2tf32(v.w));
            *(uint4*)(Ws + kk * WS_STRIDE + q * 4) = u;
        }
        __syncthreads();

        #pragma unroll
        for (int kk = 0; kk < 32; kk += 8) {
            uint32_t a[2][4];
            #pragma unroll
            for (int mt = 0; mt < 2; mt++) {
                int rbase = wrow + mt * 16;
                a[mt][0] = Xs[(rbase + gid) * XS_STRIDE + kk + tig];
                a[mt][1] = Xs[(rbase + gid + 8) * XS_STRIDE + kk + tig];
                a[mt][2] = Xs[(rbase + gid) * XS_STRIDE + kk + tig + 4];
                a[mt][3] = Xs[(rbase + gid + 8) * XS_STRIDE + kk + tig + 4];
            }
            #pragma unroll
            for (int nb = 0; nb < 8; nb++) {
                uint32_t b0 = Ws[(kk + tig) * WS_STRIDE + nb * 8 + gid];
                uint32_t b1 = Ws[(kk + tig + 4) * WS_STRIDE + nb * 8 + gid];
                #pragma unroll
                for (int mt = 0; mt < 2; mt++) {
                    asm volatile(
                        "mma.sync.aligned.m16n8k8.row.col.f32.tf32.tf32.f32 "
                        "{%0,%1,%2,%3}, {%4,%5,%6,%7}, {%8,%9}, {%0,%1,%2,%3};"
                        : "+f"(acc[mt][nb][0]), "+f"(acc[mt][nb][1]),
                          "+f"(acc[mt][nb][2]), "+f"(acc[mt][nb][3])
                        : "r"(a[mt][0]), "r"(a[mt][1]), "r"(a[mt][2]), "r"(a[mt][3]),
                          "r"(b0), "r"(b1));
                }
            }
        }
        __syncthreads();
    }

    // Fused epilogue: hs = dinv*h; agg_raw = hs (dinv[dst] deferred to gemm2)
    #pragma unroll
    for (int mt = 0; mt < 2; mt++) {
        const int rA = row0 + wrow + mt * 16 + gid;
        const int rB = rA + 8;
        float dA = (rA < n) ? g_dinv[rA] : 0.f;
        float dB = (rB < n) ? g_dinv[rB] : 0.f;
        #pragma unroll
        for (int nb = 0; nb < 8; nb++) {
            int col = nb * 8 + 2 * tig;
            if (rA < n) {
                float2 h01 = make_float2(dA * acc[mt][nb][0], dA * acc[mt][nb][1]);
                *(float2*)(g_hs  + (size_t)rA * HIDDEN + col) = h01;
                *(float2*)(g_agg + (size_t)rA * HIDDEN + col) = h01;
            }
            if (rB < n) {
                float2 h23 = make_float2(dB * acc[mt][nb][2], dB * acc[mt][nb][3]);
                *(float2*)(g_hs  + (size_t)rB * HIDDEN + col) = h23;
                *(float2*)(g_agg + (size_t)rB * HIDDEN + col) = h23;
            }
        }
    }
}

// ---------------------------------------------------------------------------
// Edge scatter: agg_raw[dst,:] += hs[src,:]  (pure gather + reduction)
// 8-thread groups, 2 edges per thread: 4 independent full-line gathers
// + 4 independent v4 reductions per thread.
// ---------------------------------------------------------------------------
__device__ __forceinline__ void red_add_v4(float* addr, float4 v) {
    asm volatile("red.global.add.v4.f32 [%0], {%1, %2, %3, %4};"
                 :: "l"(__cvta_generic_to_global(addr)),
                    "f"(v.x), "f"(v.y), "f"(v.z), "f"(v.w)
                 : "memory");
}

__global__ __launch_bounds__(256) void scatter_kernel(
    const int* __restrict__ src, const int* __restrict__ dst, int E, int n)
{
    int idx = blockIdx.x * blockDim.x + threadIdx.x;
    int g = idx >> 3, q = idx & 7;        // group of 8 threads owns edges 2g, 2g+1
    int e0 = 2 * g, e1 = 2 * g + 1;
    if (e0 >= E) return;
    bool has1 = (e1 < E);

    int2 ss = *(const int2*)(src + e0);   // e0 even -> 8B aligned
    int2 dd = *(const int2*)(dst + e0);

    bool ok0 = (unsigned)ss.x < (unsigned)n && (unsigned)dd.x < (unsigned)n;
    bool ok1 = has1 && (unsigned)ss.y < (unsigned)n && (unsigned)dd.y < (unsigned)n;

    if (ok0 && ok1) {
        const float4* h0 = (const float4*)g_hs + ss.x * 16;
        const float4* h1 = (const float4*)g_hs + ss.y * 16;
        float4 v00 = __ldg(h0 + q);
        float4 v01 = __ldg(h0 + q + 8);
        float4 v10 = __ldg(h1 + q);
        float4 v11 = __ldg(h1 + q + 8);
        float* b0 = g_agg + (size_t)dd.x * HIDDEN;
        float* b1 = g_agg + (size_t)dd.y * HIDDEN;
        red_add_v4(b0 + q * 4, v00);
        red_add_v4(b0 + (q + 8) * 4, v01);
        red_add_v4(b1 + q * 4, v10);
        red_add_v4(b1 + (q + 8) * 4, v11);
    } else if (ok0) {
        const float4* h0 = (const float4*)g_hs + ss.x * 16;
        float4 v00 = __ldg(h0 + q);
        float4 v01 = __ldg(h0 + q + 8);
        float* b0 = g_agg + (size_t)dd.x * HIDDEN;
        red_add_v4(b0 + q * 4, v00);
        red_add_v4(b0 + (q + 8) * 4, v01);
    } else if (ok1) {
        const float4* h1 = (const float4*)g_hs + ss.y * 16;
        float4 v10 = __ldg(h1 + q);
        float4 v11 = __ldg(h1 + q + 8);
        float* b1 = g_agg + (size_t)dd.y * HIDDEN;
        red_add_v4(b1 + q * 4, v10);
        red_add_v4(b1 + (q + 8) * 4, v11);
    }
}

// ---------------------------------------------------------------------------
// GEMM2: out[n,40] = relu(dinv[row]*agg_raw + b1) @ Wfc^T + bfc
// ---------------------------------------------------------------------------
__global__ __launch_bounds__(240) void gemm2_kernel(
    const float* __restrict__ b1, const float* __restrict__ Wfc,
    const float* __restrict__ bfc, float* __restrict__ out, int n)
{
    __shared__ float hs[24 * 68];
    __shared__ float Wt[64 * 40];
    __shared__ float bfs[40];

    const int tx = threadIdx.x;     // 0..9
    const int ty = threadIdx.y;     // 0..23
    const int tid = ty * 10 + tx;

    for (int idx = tid; idx < 64 * 40; idx += 240) {
        int o = idx % 40, j = idx / 40;
        Wt[j * 40 + o] = Wfc[o * 64 + j];
    }
    if (tid < 40) bfs[tid] = bfc[tid];

    const int row0 = blockIdx.x * 24;
    for (int idx = tid; idx < 24 * 16; idx += 240) {
        int r = idx >> 4, q = idx & 15;
        int grow = row0 + r;
        float4 v = make_float4(0.f, 0.f, 0.f, 0.f);
        if (grow < n) {
            float dv = g_dinv[grow];
            v = ((const float4*)g_agg)[grow * 16 + q];
            float4 bb = ((const float4*)b1)[q];
            v.x = fmaxf(fmaf(dv, v.x, bb.x), 0.f);
            v.y = fmaxf(fmaf(dv, v.y, bb.y), 0.f);
            v.z = fmaxf(fmaf(dv, v.z, bb.z), 0.f);
            v.w = fmaxf(fmaf(dv, v.w, bb.w), 0.f);
        }
        *(float4*)(hs + r * 68 + q * 4) = v;
    }
    __syncthreads();

    float4 acc = make_float4(0.f, 0.f, 0.f, 0.f);
    #pragma unroll
    for (int j = 0; j < 64; j++) {
        float h = hs[ty * 68 + j];
        float4 w = *(const float4*)(Wt + j * 40 + tx * 4);
        acc.x += h * w.x;
        acc.y += h * w.y;
        acc.z += h * w.z;
        acc.w += h * w.w;
    }

    int grow = row0 + ty;
    if (grow < n) {
        float4 bb = *(const float4*)(bfs + tx * 4);
        acc.x += bb.x; acc.y += bb.y; acc.z += bb.z; acc.w += bb.w;
        *(float4*)(out + (size_t)grow * OUTDIM + tx * 4) = acc;
    }
}

// ---------------------------------------------------------------------------
extern "C" void kernel_launch(void* const* d_in, const int* in_sizes, int n_in,
                              void* d_out, int out_size)
{
    const float* X     = (const float*)d_in[0];
    const int*   edges = (const int*)d_in[1];     // int64 downcast to int32 by harness
    const float* W1    = (const float*)d_in[2];
    const float* b1    = (const float*)d_in[3];
    const float* Wfc   = (const float*)d_in[4];
    const float* bfc   = (const float*)d_in[5];
    float* out = (float*)d_out;

    const int n = in_sizes[0] / INDIM;
    const int E = in_sizes[1] / 2;
    const int* src = edges;
    const int* dst = edges + E;

    init_deg_kernel<<<(n + 255) / 256, 256>>>(n);
    deg_accum_kernel<<<(E + 255) / 256, 256>>>(dst, E, n);
    dinv_kernel<<<(n + 255) / 256, 256>>>(n);
    gemm1_mma_kernel<<<(n + 255) / 256, 256>>>(X, W1, n);
    int groups = (E + 1) / 2;
    scatter_kernel<<<(groups * 8 + 255) / 256, 256>>>(src, dst, E, n);
    gemm2_kernel<<<(n + 23) / 24, dim3(10, 24)>>>(b1, Wfc, bfc, out, n);
}

// round 17
// speedup vs baseline: 1.1060x; 1.1033x over previous
#include <cuda_runtime.h>
#include <cstdint>

#define N_NODES 50000
#define HIDDEN  64
#define INDIM   512
#define OUTDIM  40

// Scratch (device globals)
__device__ __align__(16) float g_hs[N_NODES * HIDDEN];    // dinv[i] * h[i]
__device__ __align__(16) float g_agg[N_NODES * HIDDEN];   // raw sums (pre-dinv[dst])
__device__ __align__(16) float g_deg[N_NODES];
__device__ __align__(16) float g_dinv[N_NODES];

// ---------------------------------------------------------------------------
__global__ void init_deg_kernel(int n) {
    int i = blockIdx.x * blockDim.x + threadIdx.x;
    if (i < n) g_deg[i] = 1.0f;
}

__global__ void deg_accum_kernel(const int* __restrict__ dst, int E, int n) {
    int e = blockIdx.x * blockDim.x + threadIdx.x;
    if (e < E) {
        int d = dst[e];
        if ((unsigned)d < (unsigned)n) atomicAdd(&g_deg[d], 1.0f);
    }
}

__global__ void dinv_kernel(int n) {
    int i = blockIdx.x * blockDim.x + threadIdx.x;
    if (i < n) g_dinv[i] = rsqrtf(g_deg[i]);
}

// ---------------------------------------------------------------------------
// GEMM1 (tensor cores, tf32): h[n,64] = X[n,512] @ W1[512,64]
// cp.async double-buffered: raw f32 tiles stream in asynchronously (2 deep),
// smem->smem convert to tf32 (cvt.rna, numerics unchanged), then MMA.
// 128 rows/block, 256 threads, 8 warps x 16 rows.
// ---------------------------------------------------------------------------
__device__ __forceinline__ uint32_t f2tf32(float f) {
    uint32_t r;
    asm("cvt.rna.tf32.f32 %0, %1;" : "=r"(r) : "f"(f));
    return r;
}

__device__ __forceinline__ uint32_t smem_u32(const void* p) {
    return (uint32_t)__cvta_generic_to_shared(p);
}

__device__ __forceinline__ void cp_async16(uint32_t saddr, const void* gptr) {
    asm volatile("cp.async.cg.shared.global [%0], [%1], 16;"
                 :: "r"(saddr), "l"(gptr));
}
#define CP_COMMIT() asm volatile("cp.async.commit_group;")
#define CP_WAIT1()  asm volatile("cp.async.wait_group 1;")

#define XS_STRIDE 36
#define WS_STRIDE 72
// dynamic smem layout (uint32 words):
//   rawX: 2 x 4096 (128 rows x 32 k, f32)        [0, 8192)
//   rawW: 2 x 2048 (32 k x 64 cols, f32)         [8192, 12288)
//   Xs:   128 x 36 tf32                          [12288, 16896)
//   Ws:   32 x 72 tf32                           [16896, 19200)
#define SMEM_WORDS 19200
#define SMEM_BYTES (SMEM_WORDS * 4)

__global__ __launch_bounds__(256) void gemm1_mma_kernel(
    const float* __restrict__ X, const float* __restrict__ W, int n)
{
    extern __shared__ uint32_t smem[];
    uint32_t* rawX = smem;                    // [2][4096]
    uint32_t* rawW = smem + 8192;             // [2][2048]
    uint32_t* Xs   = smem + 12288;            // [128*36]
    uint32_t* Ws   = smem + 16896;            // [32*72]

    const int tid  = threadIdx.x;
    const int lane = tid & 31;
    const int wid  = tid >> 5;        // 0..7
    const int gid  = lane >> 2;       // 0..7
    const int tig  = lane & 3;        // 0..3
    const int wrow = wid * 16;
    const int row0 = blockIdx.x * 128;

    // Per-thread fixed load coordinates
    int xr[4], xq[4], xrr[4];
    #pragma unroll
    for (int t = 0; t < 4; t++) {
        int s = t * 256 + tid;
        xr[t] = s >> 3; xq[t] = s & 7;
        int rr = row0 + xr[t]; if (rr >= n) rr = n - 1;
        xrr[t] = rr;
    }
    int wk[2], wq[2];
    #pragma unroll
    for (int t = 0; t < 2; t++) {
        int s = t * 256 + tid;
        wk[t] = s >> 4; wq[t] = s & 15;
    }

    // Prologue: issue tile 0 into stage 0
    #pragma unroll
    for (int t = 0; t < 4; t++)
        cp_async16(smem_u32(rawX + xr[t] * 32 + xq[t] * 4),
                   X + (size_t)xrr[t] * INDIM + xq[t] * 4);
    #pragma unroll
    for (int t = 0; t < 2; t++)
        cp_async16(smem_u32(rawW + wk[t] * 64 + wq[t] * 4),
                   W + (size_t)wk[t] * HIDDEN + wq[t] * 4);
    CP_COMMIT();

    float acc[8][4] = {};

    for (int it = 0; it < 16; it++) {
        int stage = it & 1;
        // Issue next tile into the other stage (async, 2 deep)
        if (it + 1 < 16) {
            int k1 = (it + 1) * 32;
            int ns = (it + 1) & 1;
            #pragma unroll
            for (int t = 0; t < 4; t++)
                cp_async16(smem_u32(rawX + ns * 4096 + xr[t] * 32 + xq[t] * 4),
                           X + (size_t)xrr[t] * INDIM + k1 + xq[t] * 4);
            #pragma unroll
            for (int t = 0; t < 2; t++)
                cp_async16(smem_u32(rawW + ns * 2048 + wk[t] * 64 + wq[t] * 4),
                           W + (size_t)(k1 + wk[t]) * HIDDEN + wq[t] * 4);
        }
        CP_COMMIT();
        CP_WAIT1();           // tile `it` arrived
        __syncthreads();

        // Convert raw f32 -> tf32 (cvt.rna: numerics identical to baseline)
        #pragma unroll
        for (int t = 0; t < 4; t++) {
            uint4 raw = *(const uint4*)(rawX + stage * 4096 + xr[t] * 32 + xq[t] * 4);
            uint4 u = make_uint4(f2tf32(__uint_as_float(raw.x)),
                                 f2tf32(__uint_as_float(raw.y)),
                                 f2tf32(__uint_as_float(raw.z)),
                                 f2tf32(__uint_as_float(raw.w)));
            *(uint4*)(Xs + xr[t] * XS_STRIDE + xq[t] * 4) = u;
        }
        #pragma unroll
        for (int t = 0; t < 2; t++) {
            uint4 raw = *(const uint4*)(rawW + stage * 2048 + wk[t] * 64 + wq[t] * 4);
            uint4 u = make_uint4(f2tf32(__uint_as_float(raw.x)),
                                 f2tf32(__uint_as_float(raw.y)),
                                 f2tf32(__uint_as_float(raw.z)),
                                 f2tf32(__uint_as_float(raw.w)));
            *(uint4*)(Ws + wk[t] * WS_STRIDE + wq[t] * 4) = u;
        }
        __syncthreads();

        // Compute on tf32 buffers
        #pragma unroll
        for (int kk = 0; kk < 32; kk += 8) {
            uint32_t a0 = Xs[(wrow + gid) * XS_STRIDE + kk + tig];
            uint32_t a1 = Xs[(wrow + gid + 8) * XS_STRIDE + kk + tig];
            uint32_t a2 = Xs[(wrow + gid) * XS_STRIDE + kk + tig + 4];
            uint32_t a3 = Xs[(wrow + gid + 8) * XS_STRIDE + kk + tig + 4];
            #pragma unroll
            for (int nb = 0; nb < 8; nb++) {
                uint32_t b0 = Ws[(kk + tig) * WS_STRIDE + nb * 8 + gid];
                uint32_t b1 = Ws[(kk + tig + 4) * WS_STRIDE + nb * 8 + gid];
                asm volatile(
                    "mma.sync.aligned.m16n8k8.row.col.f32.tf32.tf32.f32 "
                    "{%0,%1,%2,%3}, {%4,%5,%6,%7}, {%8,%9}, {%0,%1,%2,%3};"
                    : "+f"(acc[nb][0]), "+f"(acc[nb][1]),
                      "+f"(acc[nb][2]), "+f"(acc[nb][3])
                    : "r"(a0), "r"(a1), "r"(a2), "r"(a3), "r"(b0), "r"(b1));
            }
        }
        __syncthreads();
    }

    // Fused epilogue: hs = dinv*h; agg_raw = hs (dinv[dst] deferred to gemm2)
    const int rA = row0 + wrow + gid;
    const int rB = rA + 8;
    float dA = (rA < n) ? g_dinv[rA] : 0.f;
    float dB = (rB < n) ? g_dinv[rB] : 0.f;
    #pragma unroll
    for (int nb = 0; nb < 8; nb++) {
        int col = nb * 8 + 2 * tig;
        if (rA < n) {
            float2 h01 = make_float2(dA * acc[nb][0], dA * acc[nb][1]);
            *(float2*)(g_hs  + (size_t)rA * HIDDEN + col) = h01;
            *(float2*)(g_agg + (size_t)rA * HIDDEN + col) = h01;
        }
        if (rB < n) {
            float2 h23 = make_float2(dB * acc[nb][2], dB * acc[nb][3]);
            *(float2*)(g_hs  + (size_t)rB * HIDDEN + col) = h23;
            *(float2*)(g_agg + (size_t)rB * HIDDEN + col) = h23;
        }
    }
}

// ---------------------------------------------------------------------------
// Edge scatter: agg_raw[dst,:] += hs[src,:]  (pure gather + reduction)
// 8-thread groups, 2 edges per thread (r13 form — proven best).
// ---------------------------------------------------------------------------
__device__ __forceinline__ void red_add_v4(float* addr, float4 v) {
    asm volatile("red.global.add.v4.f32 [%0], {%1, %2, %3, %4};"
                 :: "l"(__cvta_generic_to_global(addr)),
                    "f"(v.x), "f"(v.y), "f"(v.z), "f"(v.w)
                 : "memory");
}

__global__ __launch_bounds__(256) void scatter_kernel(
    const int* __restrict__ src, const int* __restrict__ dst, int E, int n)
{
    int idx = blockIdx.x * blockDim.x + threadIdx.x;
    int g = idx >> 3, q = idx & 7;
    int e0 = 2 * g, e1 = 2 * g + 1;
    if (e0 >= E) return;
    bool has1 = (e1 < E);

    int2 ss = *(const int2*)(src + e0);
    int2 dd = *(const int2*)(dst + e0);

    bool ok0 = (unsigned)ss.x < (unsigned)n && (unsigned)dd.x < (unsigned)n;
    bool ok1 = has1 && (unsigned)ss.y < (unsigned)n && (unsigned)dd.y < (unsigned)n;

    if (ok0 && ok1) {
        const float4* h0 = (const float4*)g_hs + ss.x * 16;
        const float4* h1 = (const float4*)g_hs + ss.y * 16;
        float4 v00 = __ldg(h0 + q);
        float4 v01 = __ldg(h0 + q + 8);
        float4 v10 = __ldg(h1 + q);
        float4 v11 = __ldg(h1 + q + 8);
        float* b0 = g_agg + (size_t)dd.x * HIDDEN;
        float* b1 = g_agg + (size_t)dd.y * HIDDEN;
        red_add_v4(b0 + q * 4, v00);
        red_add_v4(b0 + (q + 8) * 4, v01);
        red_add_v4(b1 + q * 4, v10);
        red_add_v4(b1 + (q + 8) * 4, v11);
    } else if (ok0) {
        const float4* h0 = (const float4*)g_hs + ss.x * 16;
        float4 v00 = __ldg(h0 + q);
        float4 v01 = __ldg(h0 + q + 8);
        float* b0 = g_agg + (size_t)dd.x * HIDDEN;
        red_add_v4(b0 + q * 4, v00);
        red_add_v4(b0 + (q + 8) * 4, v01);
    } else if (ok1) {
        const float4* h1 = (const float4*)g_hs + ss.y * 16;
        float4 v10 = __ldg(h1 + q);
        float4 v11 = __ldg(h1 + q + 8);
        float* b1 = g_agg + (size_t)dd.y * HIDDEN;
        red_add_v4(b1 + q * 4, v10);
        red_add_v4(b1 + (q + 8) * 4, v11);
    }
}

// ---------------------------------------------------------------------------
// GEMM2: out[n,40] = relu(dinv[row]*agg_raw + b1) @ Wfc^T + bfc
// ---------------------------------------------------------------------------
__global__ __launch_bounds__(240) void gemm2_kernel(
    const float* __restrict__ b1, const float* __restrict__ Wfc,
    const float* __restrict__ bfc, float* __restrict__ out, int n)
{
    __shared__ float hs[24 * 68];
    __shared__ float Wt[64 * 40];
    __shared__ float bfs[40];

    const int tx = threadIdx.x;     // 0..9
    const int ty = threadIdx.y;     // 0..23
    const int tid = ty * 10 + tx;

    for (int idx = tid; idx < 64 * 40; idx += 240) {
        int o = idx % 40, j = idx / 40;
        Wt[j * 40 + o] = Wfc[o * 64 + j];
    }
    if (tid < 40) bfs[tid] = bfc[tid];

    const int row0 = blockIdx.x * 24;
    for (int idx = tid; idx < 24 * 16; idx += 240) {
        int r = idx >> 4, q = idx & 15;
        int grow = row0 + r;
        float4 v = make_float4(0.f, 0.f, 0.f, 0.f);
        if (grow < n) {
            float dv = g_dinv[grow];
            v = ((const float4*)g_agg)[grow * 16 + q];
            float4 bb = ((const float4*)b1)[q];
            v.x = fmaxf(fmaf(dv, v.x, bb.x), 0.f);
            v.y = fmaxf(fmaf(dv, v.y, bb.y), 0.f);
            v.z = fmaxf(fmaf(dv, v.z, bb.z), 0.f);
            v.w = fmaxf(fmaf(dv, v.w, bb.w), 0.f);
        }
        *(float4*)(hs + r * 68 + q * 4) = v;
    }
    __syncthreads();

    float4 acc = make_float4(0.f, 0.f, 0.f, 0.f);
    #pragma unroll
    for (int j = 0; j < 64; j++) {
        float h = hs[ty * 68 + j];
        float4 w = *(const float4*)(Wt + j * 40 + tx * 4);
        acc.x += h * w.x;
        acc.y += h * w.y;
        acc.z += h * w.z;
        acc.w += h * w.w;
    }

    int grow = row0 + ty;
    if (grow < n) {
        float4 bb = *(const float4*)(bfs + tx * 4);
        acc.x += bb.x; acc.y += bb.y; acc.z += bb.z; acc.w += bb.w;
        *(float4*)(out + (size_t)grow * OUTDIM + tx * 4) = acc;
    }
}

// ---------------------------------------------------------------------------
extern "C" void kernel_launch(void* const* d_in, const int* in_sizes, int n_in,
                              void* d_out, int out_size)
{
    const float* X     = (const float*)d_in[0];
    const int*   edges = (const int*)d_in[1];     // int64 downcast to int32 by harness
    const float* W1    = (const float*)d_in[2];
    const float* b1    = (const float*)d_in[3];
    const float* Wfc   = (const float*)d_in[4];
    const float* bfc   = (const float*)d_in[5];
    float* out = (float*)d_out;

    const int n = in_sizes[0] / INDIM;
    const int E = in_sizes[1] / 2;
    const int* src = edges;
    const int* dst = edges + E;

    static int smem_set = 0;
    if (!smem_set) {
        cudaFuncSetAttribute(gemm1_mma_kernel,
                             cudaFuncAttributeMaxDynamicSharedMemorySize,
                             SMEM_BYTES);
        smem_set = 1;
    }

    init_deg_kernel<<<(n + 255) / 256, 256>>>(n);
    deg_accum_kernel<<<(E + 255) / 256, 256>>>(dst, E, n);
    dinv_kernel<<<(n + 255) / 256, 256>>>(n);
    gemm1_mma_kernel<<<(n + 127) / 128, 256, SMEM_BYTES>>>(X, W1, n);
    int groups = (E + 1) / 2;
    scatter_kernel<<<(groups * 8 + 255) / 256, 256>>>(src, dst, E, n);
    gemm2_kernel<<<(n + 23) / 24, dim3(10, 24)>>>(b1, Wfc, bfc, out, n);
}